// round 14
// baseline (speedup 1.0000x reference)
#include <cuda_runtime.h>
#include <cuda_fp16.h>
#include <cstdint>

// Problem constants
#define Mq 16384   // B*N rows
#define Kq 8192    // codebook size
#define Dq 256     // dim

#define BM 128
#define BN 128
#define BK 64      // halves per k-chunk (128 bytes)
#define NT 8       // n-tiles per CTA
#define NITER (NT * (Dq / BK))   // 32
#define ROWB (Dq * 2)            // 512 bytes per fp16 row

#define T_PUSH 2.0f   // certified candidate margin (hard bound ~1.57)
#define CAND_CAP 256

// ---------------------------------------------------------------------------
// Static device scratch (no cudaMalloc allowed)
// ---------------------------------------------------------------------------
__device__ __align__(16) __half g_A[Mq * Dq];   // 8 MB  (hx)
__device__ __align__(16) __half g_B[Kq * Dq];   // 4 MB  (hc)
__device__ float g_c2[Kq];
__device__ int g_ccount[Mq];
__device__ uint2 g_cand[Mq * CAND_CAP];          // (d~ bits, k)
__device__ int g_idx[Mq];

// ---------------------------------------------------------------------------
// Helpers
// ---------------------------------------------------------------------------
__device__ __forceinline__ uint32_t smem_u32(const void* p) {
    uint32_t a;
    asm("{ .reg .u64 t; cvta.to.shared.u64 t, %1; cvt.u32.u64 %0, t; }" : "=r"(a) : "l"(p));
    return a;
}
#define CP_ASYNC16(dst, src) \
    asm volatile("cp.async.cg.shared.global [%0], [%1], 16;" :: "r"(dst), "l"(src))
#define CP_COMMIT() asm volatile("cp.async.commit_group;")
#define CP_WAIT(n)  asm volatile("cp.async.wait_group %0;" :: "n"(n))

#define LDMATRIX_X4(r0, r1, r2, r3, addr)                                     \
    asm volatile("ldmatrix.sync.aligned.m8n8.x4.shared.b16 {%0,%1,%2,%3}, [%4];" \
                 : "=r"(r0), "=r"(r1), "=r"(r2), "=r"(r3) : "r"(addr))

#define MMA16816(c, a, b0, b1)                                                \
    asm volatile(                                                             \
        "mma.sync.aligned.m16n8k16.row.col.f32.f16.f16.f32 "                  \
        "{%0,%1,%2,%3}, {%4,%5,%6,%7}, {%8,%9}, {%0,%1,%2,%3};"               \
        : "+f"((c)[0]), "+f"((c)[1]), "+f"((c)[2]), "+f"((c)[3])              \
        : "r"((a)[0]), "r"((a)[1]), "r"((a)[2]), "r"((a)[3]), "r"(b0), "r"(b1))

// ---------------------------------------------------------------------------
// Prep kernels
// ---------------------------------------------------------------------------
__device__ __forceinline__ uint2 hi4(const float4 v) {
    __half2 h01 = __halves2half2(__float2half_rn(v.x), __float2half_rn(v.y));
    __half2 h23 = __halves2half2(__float2half_rn(v.z), __float2half_rn(v.w));
    uint2 r;
    r.x = *reinterpret_cast<uint32_t*>(&h01);
    r.y = *reinterpret_cast<uint32_t*>(&h23);
    return r;
}

// x -> fp16 hi; also zero candidate counters (every launch; graph replays)
__global__ void split_x_kernel(const float* __restrict__ x) {
    int i = blockIdx.x * 256 + threadIdx.x;       // over Mq*Dq/4 = 1048576
    ((uint2*)g_A)[i] = hi4(((const float4*)x)[i]);
    if (i < Mq) g_ccount[i] = 0;
}

// codebook -> fp16 hi, fused with c2[k] = ||c_k||^2. One warp per code row.
__global__ void split_c2_kernel(const float* __restrict__ cb) {
    const int warp = (blockIdx.x * 256 + threadIdx.x) >> 5;
    const int lane = threadIdx.x & 31;
    if (warp >= Kq) return;
    const float* row = cb + (size_t)warp * Dq;
    __half* hrow = g_B + (size_t)warp * Dq;
    float s = 0.f;
#pragma unroll
    for (int j = 0; j < 8; j++) {
        float v = row[j * 32 + lane];
        s += v * v;
        hrow[j * 32 + lane] = __float2half_rn(v);
    }
#pragma unroll
    for (int o = 16; o; o >>= 1) s += __shfl_xor_sync(0xffffffffu, s, o);
    if (lane == 0) g_c2[warp] = s;
}

// ---------------------------------------------------------------------------
// Phase 1: hh-GEMM (HMMA) + candidate push, A-resident multi-N-tile CTAs.
// Grid (Mq/BM, Kq/(BN*NT)) = (128, 8). 256 threads = 8 warps (4M x 2N).
// A tile (128x256 fp16 = 64KB) resident; B streamed 2-slot double buffered;
// c2 tile rides along (double buffered). Epilogue per n-tile.
// ---------------------------------------------------------------------------
#define A_OFF 0                     // 65536
#define B_OFF 65536                 // 2 x 16384
#define C2_OFF (B_OFF + 32768)      // 2 x 512
#define RM_OFF (C2_OFF + 1024)      // 1024
#define SMEM_TOTAL (RM_OFF + 1024)  // 100352 -> 2 CTAs/SM

__global__ __launch_bounds__(256, 2) void vq_mma_kernel() {
    extern __shared__ char smem[];
    const uint32_t sb = smem_u32(smem);
    const int tid = threadIdx.x;
    const int wid = tid >> 5, lane = tid & 31;
    const int m0 = blockIdx.x * BM;
    const int n0 = blockIdx.y * (NT * BN);
    const int wm = wid & 3, wn = wid >> 2;

    float* rowmin = (float*)(smem + RM_OFF);   // [128][2]

    // ---- B-load addressing (4 segs of 16B per thread per chunk) ----
    const int rr = tid >> 3, q = tid & 7;
    const uint32_t dB0 = rr * 128 + ((q ^ (rr & 7)) << 4);
    const char* srcB0 = (const char*)g_B + (size_t)(n0 + rr) * ROWB + q * 16;

    // ---- A resident load: 64KB = 16 segs of 16B per thread, one group ----
#pragma unroll
    for (int i = 0; i < 16; i++) {
        int e = tid + i * 256;
        int kc = e >> 10, rem = e & 1023, r = rem >> 3, qq = rem & 7;
        uint32_t dst = sb + A_OFF + kc * 16384 + r * 128 + ((qq ^ (r & 7)) << 4);
        const char* src = (const char*)g_A + (size_t)(m0 + r) * ROWB + kc * 128 + qq * 16;
        CP_ASYNC16(dst, src);
    }
    CP_COMMIT();

    auto issueB = [&](int j) {
        const int nt = j >> 2, kc = j & 3, slot = j & 1;
        const uint32_t base = sb + B_OFF + slot * 16384;
        const char* s = srcB0 + (size_t)nt * (BN * ROWB) + kc * 128;
#pragma unroll
        for (int i = 0; i < 4; i++)
            CP_ASYNC16(base + dB0 + i * 4096, s + i * (size_t)(32 * ROWB));
        if (kc == 0 && tid < 32)   // c2 tile for nt (512B), double buffered
            CP_ASYNC16(sb + C2_OFF + (nt & 1) * 512 + tid * 16,
                       (const char*)(g_c2 + n0 + nt * BN) + tid * 16);
        CP_COMMIT();
    };

    issueB(0);
    issueB(1);

    // ---- ldmatrix addressing ----
    const int rA = (lane & 7) + ((lane >> 3) & 1) * 8;
    const int sA = (lane >> 4) & 1;
    const int rB = (lane & 7) + ((lane >> 4) & 1) * 8;
    const int sB = (lane >> 3) & 1;
    const int l7 = lane & 7;

    uint32_t aoff[2], boff[4];
#pragma unroll
    for (int mi = 0; mi < 2; mi++) aoff[mi] = (wm * 32 + mi * 16 + rA) * 128;
#pragma unroll
    for (int nb = 0; nb < 4; nb++) boff[nb] = (wn * 64 + nb * 16 + rB) * 128;

    float acc[2][8][4];
#pragma unroll
    for (int mi = 0; mi < 2; mi++)
#pragma unroll
        for (int nj = 0; nj < 8; nj++)
#pragma unroll
            for (int r = 0; r < 4; r++) acc[mi][nj][r] = 0.f;

    for (int it = 0; it < NITER; it++) {
        const int kc = it & 3, slot = it & 1, nt = it >> 2;
        CP_WAIT(1);
        __syncthreads();

        const uint32_t stA = sb + A_OFF + kc * 16384;
        const uint32_t stB = sb + B_OFF + slot * 16384;
#pragma unroll
        for (int ks = 0; ks < 4; ks++) {
            const uint32_t segA = (((ks * 2 + sA) ^ l7) << 4);
            const uint32_t segB = (((ks * 2 + sB) ^ l7) << 4);
            uint32_t a[2][4], b[4][4];
#pragma unroll
            for (int mi = 0; mi < 2; mi++)
                LDMATRIX_X4(a[mi][0], a[mi][1], a[mi][2], a[mi][3], stA + aoff[mi] + segA);
#pragma unroll
            for (int nb = 0; nb < 4; nb++)
                LDMATRIX_X4(b[nb][0], b[nb][1], b[nb][2], b[nb][3], stB + boff[nb] + segB);
#pragma unroll
            for (int mi = 0; mi < 2; mi++)
#pragma unroll
                for (int nj = 0; nj < 8; nj++)
                    MMA16816(acc[mi][nj], a[mi], b[nj >> 1][(nj & 1) * 2],
                             b[nj >> 1][(nj & 1) * 2 + 1]);
        }
        __syncthreads();                       // all reads done before reuse
        if (it + 2 < NITER) issueB(it + 2);    // overwrites slot just consumed

        if (kc == 3) {
            // ---- epilogue for n-tile nt (overlaps in-flight B loads) ----
            const float* c2s = (const float*)(smem + C2_OFF + (nt & 1) * 512);

            // pass 1: per-warp per-row local min -> smem
#pragma unroll
            for (int mi = 0; mi < 2; mi++) {
#pragma unroll
                for (int h = 0; h < 2; h++) {
                    float lmin = __int_as_float(0x7f800000);
#pragma unroll
                    for (int nj = 0; nj < 8; nj++) {
                        int col = wn * 64 + nj * 8 + (lane & 3) * 2;
                        float d0 = fmaf(-2.f, acc[mi][nj][h * 2 + 0], c2s[col]);
                        float d1 = fmaf(-2.f, acc[mi][nj][h * 2 + 1], c2s[col + 1]);
                        lmin = fminf(lmin, fminf(d0, d1));
                    }
#pragma unroll
                    for (int off = 1; off <= 2; off <<= 1)
                        lmin = fminf(lmin, __shfl_xor_sync(0xffffffffu, lmin, off));
                    if ((lane & 3) == 0) {
                        int rl = wm * 32 + mi * 16 + h * 8 + (lane >> 2);
                        rowmin[rl * 2 + wn] = lmin;
                    }
                }
            }
            __syncthreads();

            // pass 2: push candidates vs CTA-wide row min + T, then reset acc
#pragma unroll
            for (int mi = 0; mi < 2; mi++) {
#pragma unroll
                for (int h = 0; h < 2; h++) {
                    const int rl = wm * 32 + mi * 16 + h * 8 + (lane >> 2);
                    const float thr = fminf(rowmin[rl * 2], rowmin[rl * 2 + 1]) + T_PUSH;
                    const int m = m0 + rl;
#pragma unroll
                    for (int nj = 0; nj < 8; nj++) {
#pragma unroll
                        for (int e = 0; e < 2; e++) {
                            float d = fmaf(-2.f, acc[mi][nj][h * 2 + e],
                                           c2s[wn * 64 + nj * 8 + (lane & 3) * 2 + e]);
                            if (d <= thr) {
                                int k = n0 + nt * BN + wn * 64 + nj * 8 + (lane & 3) * 2 + e;
                                int pos = atomicAdd(&g_ccount[m], 1);
                                if (pos < CAND_CAP)
                                    g_cand[m * CAND_CAP + pos] =
                                        make_uint2(__float_as_uint(d), (unsigned)k);
                            }
                            acc[mi][nj][h * 2 + e] = 0.f;
                        }
                    }
                }
            }
        }
    }
}

// ---------------------------------------------------------------------------
// Phase 2: resolve. One warp per row. Fast path: global d~min over candidates,
// exact fp32 rescore of those within T (tie -> lowest k). Overflow path
// (cnt > CAND_CAP): exact full scan -- correctness never depends on capacity.
// ---------------------------------------------------------------------------
__global__ __launch_bounds__(256) void resolve_kernel(const float* __restrict__ x,
                                                      const float* __restrict__ cb) {
    __shared__ float sx[8][Dq];
    const int warp = (blockIdx.x * 256 + threadIdx.x) >> 5;
    const int wloc = (threadIdx.x >> 5);
    const int lane = threadIdx.x & 31;
    if (warp >= Mq) return;
    const int m = warp;

    float xr[8];
#pragma unroll
    for (int j = 0; j < 8; j++) {
        xr[j] = x[(size_t)m * Dq + lane + 32 * j];
        sx[wloc][lane + 32 * j] = xr[j];
    }

    const int rawcnt = g_ccount[m];
    float bestd = __int_as_float(0x7f800000);
    int bestk = Kq;

    if (rawcnt <= CAND_CAP) {
        float dmin = __int_as_float(0x7f800000);
        for (int i = lane; i < rawcnt; i += 32)
            dmin = fminf(dmin, __uint_as_float(g_cand[m * CAND_CAP + i].x));
#pragma unroll
        for (int o = 16; o; o >>= 1)
            dmin = fminf(dmin, __shfl_xor_sync(0xffffffffu, dmin, o));
        const float thr = dmin + T_PUSH;

        for (int i = 0; i < rawcnt; i++) {
            uint2 ent = g_cand[m * CAND_CAP + i];
            if (__uint_as_float(ent.x) > thr) continue;
            int k = (int)ent.y;
            const float* crow = cb + (size_t)k * Dq;
            float s = 0.f;
#pragma unroll
            for (int j = 0; j < 8; j++) s += xr[j] * crow[lane + 32 * j];
#pragma unroll
            for (int o = 16; o; o >>= 1) s += __shfl_xor_sync(0xffffffffu, s, o);
            float d = fmaf(-2.f, s, g_c2[k]);
            if (d < bestd || (d == bestd && k < bestk)) { bestd = d; bestk = k; }
        }
    } else {
        for (int k = lane; k < Kq; k += 32) {
            const float* crow = cb + (size_t)k * Dq;
            float s = 0.f;
#pragma unroll 8
            for (int d = 0; d < Dq; d++) s += sx[wloc][d] * crow[d];
            float dd = fmaf(-2.f, s, g_c2[k]);
            if (dd < bestd || (dd == bestd && k < bestk)) { bestd = dd; bestk = k; }
        }
#pragma unroll
        for (int o = 16; o; o >>= 1) {
            float od = __shfl_xor_sync(0xffffffffu, bestd, o);
            int ok = __shfl_xor_sync(0xffffffffu, bestk, o);
            if (od < bestd || (od == bestd && ok < bestk)) { bestd = od; bestk = ok; }
        }
    }
    if (lane == 0) g_idx[m] = bestk;
}

// ---------------------------------------------------------------------------
// Gather + write tuple output: [x_recon | z_e | z_q | indices-as-float]
// ---------------------------------------------------------------------------
__global__ void gather_kernel(const float* __restrict__ x,
                              const float* __restrict__ cb,
                              float* __restrict__ out) {
    const int m = blockIdx.x;
    const int idx = g_idx[m];

    const float4* crow = (const float4*)(cb + (size_t)idx * Dq);
    const float4* xrow = (const float4*)(x + (size_t)m * Dq);
    const size_t BND = (size_t)Mq * Dq;
    float4* o0 = (float4*)(out) + (size_t)m * (Dq / 4);
    float4* o1 = (float4*)(out + BND) + (size_t)m * (Dq / 4);
    float4* o2 = (float4*)(out + 2 * BND) + (size_t)m * (Dq / 4);

    const int t = threadIdx.x;  // 0..63
    float4 c = crow[t];
    o0[t] = c;
    o2[t] = c;
    o1[t] = xrow[t];
    if (t == 0) out[3 * BND + m] = (float)idx;
}

// ---------------------------------------------------------------------------
extern "C" void kernel_launch(void* const* d_in, const int* in_sizes, int n_in,
                              void* d_out, int out_size) {
    const float* x = (const float*)d_in[0];    // (B, N, D) fp32
    const float* cb = (const float*)d_in[1];   // (K, D) fp32
    float* out = (float*)d_out;
    (void)in_sizes; (void)n_in; (void)out_size;

    split_x_kernel<<<Mq * Dq / 4 / 256, 256>>>(x);
    split_c2_kernel<<<Kq / 8, 256>>>(cb);

    cudaFuncSetAttribute(vq_mma_kernel,
                         cudaFuncAttributeMaxDynamicSharedMemorySize, SMEM_TOTAL);
    dim3 grid(Mq / BM, Kq / (BN * NT));
    vq_mma_kernel<<<grid, 256, SMEM_TOTAL>>>();

    resolve_kernel<<<(Mq * 32 + 255) / 256, 256>>>(x, cb);
    gather_kernel<<<Mq, 64>>>(x, cb, out);
}